// round 1
// baseline (speedup 1.0000x reference)
#include <cuda_runtime.h>
#include <math.h>

// Problem constants
#define Bn 4
#define Tn 4096
#define Dn 2048
#define Hn 256
#define Wn 4
#define Mn (Bn * Tn)        // 16384 tokens
#define N2 (Dn * Wn)        // 8192 flat columns

// Tiling
#define BM 128
#define BN 128
#define BK 16
#define TM 8
#define TN 8
#define NTHREADS 256

// Scratch for h = silu(x @ w1): [16384, 256] fp32 (67 MB, static device global)
__device__ float g_h[(size_t)Mn * Hn];

__device__ __forceinline__ float silu_f(float v) {
    return v / (1.0f + __expf(-v));
}

// ---------------------------------------------------------------------------
// Stage 1: g_h = silu(X[16384,2048] @ W1[2048,256])
// grid (N/BN=2, M/BM=128), 256 threads, 128x128x16 register-tiled SGEMM
// ---------------------------------------------------------------------------
__global__ __launch_bounds__(NTHREADS) void gemm1_silu_kernel(
    const float* __restrict__ X,    // [Mn, Dn]
    const float* __restrict__ W1)   // [Dn, Hn]
{
    __shared__ float As[BK][BM];
    __shared__ float Bs[BK][BN];

    const int K = Dn;               // 2048
    const int ldb = Hn;             // 256
    const int m0 = blockIdx.y * BM;
    const int n0 = blockIdx.x * BN;
    const int tid = threadIdx.x;
    const int trow = tid >> 4;      // 0..15
    const int tcol = tid & 15;      // 0..15

    float acc[TM][TN] = {};

    for (int k0 = 0; k0 < K; k0 += BK) {
        // Load A tile (128 x 16), transposed into As[k][m]. 2 float4 per thread.
        #pragma unroll
        for (int i = 0; i < 2; i++) {
            int idx = tid * 2 + i;          // 0..511
            int row = idx >> 2;             // 0..127
            int kq  = (idx & 3) * 4;        // 0,4,8,12
            float4 v = *(const float4*)(X + (size_t)(m0 + row) * K + k0 + kq);
            As[kq + 0][row] = v.x;
            As[kq + 1][row] = v.y;
            As[kq + 2][row] = v.z;
            As[kq + 3][row] = v.w;
        }
        // Load B tile (16 x 128). 2 float4 per thread.
        #pragma unroll
        for (int i = 0; i < 2; i++) {
            int idx = tid * 2 + i;          // 0..511
            int row = idx >> 5;             // k: 0..15
            int c4  = (idx & 31) * 4;       // 0..124
            *(float4*)&Bs[row][c4] =
                *(const float4*)(W1 + (size_t)(k0 + row) * ldb + n0 + c4);
        }
        __syncthreads();

        #pragma unroll
        for (int k = 0; k < BK; k++) {
            float a[TM], b[TN];
            #pragma unroll
            for (int i = 0; i < TM; i++) a[i] = As[k][trow * TM + i];
            #pragma unroll
            for (int j = 0; j < TN; j++) b[j] = Bs[k][tcol * TN + j];
            #pragma unroll
            for (int i = 0; i < TM; i++)
                #pragma unroll
                for (int j = 0; j < TN; j++)
                    acc[i][j] += a[i] * b[j];
        }
        __syncthreads();
    }

    // Epilogue: silu + store to g_h
    #pragma unroll
    for (int i = 0; i < TM; i++) {
        const int m = m0 + trow * TM + i;
        float* dst = &g_h[(size_t)m * Hn + n0 + tcol * TN];
        #pragma unroll
        for (int j = 0; j < TN; j++)
            dst[j] = silu_f(acc[i][j]);
    }
}

// ---------------------------------------------------------------------------
// Stage 2: flat = g_h[16384,256] @ W2[256,8192] + b2, then fused causal
// depthwise dynamic conv + silu -> OUT[16384, 2048].
// Each thread's TN=8 columns = 2 channels d x 4 taps w.
// grid (N2/BN=64, M/BM=128), 256 threads.
// ---------------------------------------------------------------------------
__global__ __launch_bounds__(NTHREADS) void gemm2_conv_kernel(
    const float* __restrict__ X,    // [Mn, Dn] (original input)
    const float* __restrict__ W2,   // [Hn, N2]
    const float* __restrict__ B2,   // [N2]
    float* __restrict__ OUT)        // [Mn, Dn]
{
    __shared__ float As[BK][BM];
    __shared__ float Bs[BK][BN];

    const int K = Hn;               // 256
    const int ldb = N2;             // 8192
    const int m0 = blockIdx.y * BM;
    const int n0 = blockIdx.x * BN;
    const int tid = threadIdx.x;
    const int trow = tid >> 4;
    const int tcol = tid & 15;

    float acc[TM][TN] = {};

    for (int k0 = 0; k0 < K; k0 += BK) {
        #pragma unroll
        for (int i = 0; i < 2; i++) {
            int idx = tid * 2 + i;
            int row = idx >> 2;
            int kq  = (idx & 3) * 4;
            float4 v = *(const float4*)(g_h + (size_t)(m0 + row) * K + k0 + kq);
            As[kq + 0][row] = v.x;
            As[kq + 1][row] = v.y;
            As[kq + 2][row] = v.z;
            As[kq + 3][row] = v.w;
        }
        #pragma unroll
        for (int i = 0; i < 2; i++) {
            int idx = tid * 2 + i;
            int row = idx >> 5;
            int c4  = (idx & 31) * 4;
            *(float4*)&Bs[row][c4] =
                *(const float4*)(W2 + (size_t)(k0 + row) * ldb + n0 + c4);
        }
        __syncthreads();

        #pragma unroll
        for (int k = 0; k < BK; k++) {
            float a[TM], b[TN];
            #pragma unroll
            for (int i = 0; i < TM; i++) a[i] = As[k][trow * TM + i];
            #pragma unroll
            for (int j = 0; j < TN; j++) b[j] = Bs[k][tcol * TN + j];
            #pragma unroll
            for (int i = 0; i < TM; i++)
                #pragma unroll
                for (int j = 0; j < TN; j++)
                    acc[i][j] += a[i] * b[j];
        }
        __syncthreads();
    }

    // Fused conv + silu epilogue.
    // Block rows are 128 contiguous tokens; 128 | 4096 so a block never
    // spans a batch boundary.
    const int batch = m0 / Tn;
    const int tt0   = (m0 % Tn) + trow * TM;   // first token (within batch) of this thread
    const float* xb = X + (size_t)batch * Tn * Dn;

    #pragma unroll
    for (int dd = 0; dd < 2; dd++) {
        const int d = (n0 + tcol * TN) / Wn + dd;   // channel index

        // Sliding x window: rows tt0-3 .. tt0+7 of column d (11 values).
        float xv[TM + Wn - 1];
        #pragma unroll
        for (int j = 0; j < TM + Wn - 1; j++) {
            int t = tt0 - (Wn - 1) + j;
            xv[j] = (t >= 0) ? xb[(size_t)t * Dn + d] : 0.0f;
        }

        float bias[Wn];
        #pragma unroll
        for (int w = 0; w < Wn; w++) bias[w] = B2[Wn * d + w];

        #pragma unroll
        for (int i = 0; i < TM; i++) {
            float o = 0.0f;
            #pragma unroll
            for (int w = 0; w < Wn; w++)
                o += (acc[i][dd * Wn + w] + bias[w]) * xv[i + w];
            OUT[(size_t)(m0 + trow * TM + i) * Dn + d] = silu_f(o);
        }
    }
}

// ---------------------------------------------------------------------------
extern "C" void kernel_launch(void* const* d_in, const int* in_sizes, int n_in,
                              void* d_out, int out_size) {
    const float* x  = (const float*)d_in[0];   // [4,4096,2048]
    const float* w1 = (const float*)d_in[1];   // [2048,256]
    const float* w2 = (const float*)d_in[2];   // [256,8192]
    const float* b2 = (const float*)d_in[3];   // [8192]
    float* out = (float*)d_out;

    dim3 grid1(Hn / BN, Mn / BM);   // (2, 128)
    gemm1_silu_kernel<<<grid1, NTHREADS>>>(x, w1);

    dim3 grid2(N2 / BN, Mn / BM);   // (64, 128)
    gemm2_conv_kernel<<<grid2, NTHREADS>>>(x, w2, b2, out);
}

// round 2
// speedup vs baseline: 1.0196x; 1.0196x over previous
#include <cuda_runtime.h>
#include <math.h>

// Problem constants
#define Bn 4
#define Tn 4096
#define Dn 2048
#define Hn 256
#define Wn 4
#define Mn (Bn * Tn)        // 16384 tokens
#define N2 (Dn * Wn)        // 8192 flat columns

// Tiling
#define BM 128
#define BN 128
#define BK 16
#define TM 8
#define TN 8
#define NTHREADS 256

// Scratch for h = silu(x @ w1): [16384, 256] fp32 (16.8 MB, static device global)
__device__ float g_h[(size_t)Mn * Hn];

__device__ __forceinline__ float silu_f(float v) {
    return v / (1.0f + __expf(-v));
}

// ---------------------------------------------------------------------------
// Shared double-buffered 128x128x16 SGEMM core.
// A is staged transposed As[k][m]; B row-major Bs[k][n].
// Register-prefetch LDG -> compute -> STS -> single __syncthreads per k-tile.
// ---------------------------------------------------------------------------
struct FragAcc {
    float acc[TM][TN];
};

__device__ __forceinline__ void sgemm_core(
    const float* __restrict__ A, int lda,      // [*, lda], row m0.. used
    const float* __restrict__ Bm, int ldb,     // [K, ldb]
    int K, int m0, int n0, int tid,
    float (&As)[2][BK][BM], float (&Bs)[2][BK][BN],
    float (&acc)[TM][TN])
{
    const int trow = tid >> 4;      // 0..15
    const int tcol = tid & 15;      // 0..15

    // per-thread load coords (2 float4 each for A and B)
    const int a_row0 = (tid * 2) >> 2;          // 0..127
    const int a_kq0  = ((tid * 2) & 3) * 4;
    const int a_row1 = (tid * 2 + 1) >> 2;
    const int a_kq1  = ((tid * 2 + 1) & 3) * 4;
    const int b_row0 = (tid * 2) >> 5;          // 0..15
    const int b_c0   = ((tid * 2) & 31) * 4;
    const int b_row1 = (tid * 2 + 1) >> 5;
    const int b_c1   = ((tid * 2 + 1) & 31) * 4;

    float4 pa0, pa1, pb0, pb1;

    // ---- prologue: load tile 0 ----
    pa0 = *(const float4*)(A + (size_t)(m0 + a_row0) * lda + a_kq0);
    pa1 = *(const float4*)(A + (size_t)(m0 + a_row1) * lda + a_kq1);
    pb0 = *(const float4*)(Bm + (size_t)b_row0 * ldb + n0 + b_c0);
    pb1 = *(const float4*)(Bm + (size_t)b_row1 * ldb + n0 + b_c1);

    As[0][a_kq0 + 0][a_row0] = pa0.x;
    As[0][a_kq0 + 1][a_row0] = pa0.y;
    As[0][a_kq0 + 2][a_row0] = pa0.z;
    As[0][a_kq0 + 3][a_row0] = pa0.w;
    As[0][a_kq1 + 0][a_row1] = pa1.x;
    As[0][a_kq1 + 1][a_row1] = pa1.y;
    As[0][a_kq1 + 2][a_row1] = pa1.z;
    As[0][a_kq1 + 3][a_row1] = pa1.w;
    *(float4*)&Bs[0][b_row0][b_c0] = pb0;
    *(float4*)&Bs[0][b_row1][b_c1] = pb1;
    __syncthreads();

    const int KT = K / BK;
    for (int kt = 0; kt < KT; kt++) {
        const int cur = kt & 1;
        const bool has_next = (kt + 1 < KT);

        if (has_next) {
            const int k0 = (kt + 1) * BK;
            pa0 = *(const float4*)(A + (size_t)(m0 + a_row0) * lda + k0 + a_kq0);
            pa1 = *(const float4*)(A + (size_t)(m0 + a_row1) * lda + k0 + a_kq1);
            pb0 = *(const float4*)(Bm + (size_t)(k0 + b_row0) * ldb + n0 + b_c0);
            pb1 = *(const float4*)(Bm + (size_t)(k0 + b_row1) * ldb + n0 + b_c1);
        }

        // compute on buf cur with 128-bit fragment loads
        #pragma unroll
        for (int k = 0; k < BK; k++) {
            float4 a0 = *(const float4*)&As[cur][k][trow * TM];
            float4 a1 = *(const float4*)&As[cur][k][trow * TM + 4];
            float4 b0 = *(const float4*)&Bs[cur][k][tcol * TN];
            float4 b1 = *(const float4*)&Bs[cur][k][tcol * TN + 4];
            float a[TM] = {a0.x, a0.y, a0.z, a0.w, a1.x, a1.y, a1.z, a1.w};
            float b[TN] = {b0.x, b0.y, b0.z, b0.w, b1.x, b1.y, b1.z, b1.w};
            #pragma unroll
            for (int i = 0; i < TM; i++)
                #pragma unroll
                for (int j = 0; j < TN; j++)
                    acc[i][j] += a[i] * b[j];
        }

        if (has_next) {
            const int nxt = cur ^ 1;
            As[nxt][a_kq0 + 0][a_row0] = pa0.x;
            As[nxt][a_kq0 + 1][a_row0] = pa0.y;
            As[nxt][a_kq0 + 2][a_row0] = pa0.z;
            As[nxt][a_kq0 + 3][a_row0] = pa0.w;
            As[nxt][a_kq1 + 0][a_row1] = pa1.x;
            As[nxt][a_kq1 + 1][a_row1] = pa1.y;
            As[nxt][a_kq1 + 2][a_row1] = pa1.z;
            As[nxt][a_kq1 + 3][a_row1] = pa1.w;
            *(float4*)&Bs[nxt][b_row0][b_c0] = pb0;
            *(float4*)&Bs[nxt][b_row1][b_c1] = pb1;
        }
        __syncthreads();
    }
}

// ---------------------------------------------------------------------------
// Stage 1: g_h = silu(X[16384,2048] @ W1[2048,256])
// ---------------------------------------------------------------------------
__global__ __launch_bounds__(NTHREADS, 2) void gemm1_silu_kernel(
    const float* __restrict__ X,
    const float* __restrict__ W1)
{
    __shared__ __align__(16) float As[2][BK][BM];
    __shared__ __align__(16) float Bs[2][BK][BN];

    const int m0 = blockIdx.y * BM;
    const int n0 = blockIdx.x * BN;
    const int tid = threadIdx.x;
    const int trow = tid >> 4;
    const int tcol = tid & 15;

    float acc[TM][TN] = {};
    sgemm_core(X, Dn, W1, Hn, Dn, m0, n0, tid, As, Bs, acc);

    #pragma unroll
    for (int i = 0; i < TM; i++) {
        const int m = m0 + trow * TM + i;
        float* dst = &g_h[(size_t)m * Hn + n0 + tcol * TN];
        #pragma unroll
        for (int j = 0; j < TN; j++)
            dst[j] = silu_f(acc[i][j]);
    }
}

// ---------------------------------------------------------------------------
// Stage 2: flat = g_h @ W2 + b2, fused causal depthwise conv + silu.
// Each thread's TN=8 columns = 2 channels d x 4 taps w.
// ---------------------------------------------------------------------------
__global__ __launch_bounds__(NTHREADS, 2) void gemm2_conv_kernel(
    const float* __restrict__ X,
    const float* __restrict__ W2,
    const float* __restrict__ B2,
    float* __restrict__ OUT)
{
    __shared__ __align__(16) float As[2][BK][BM];
    __shared__ __align__(16) float Bs[2][BK][BN];

    const int m0 = blockIdx.y * BM;
    const int n0 = blockIdx.x * BN;
    const int tid = threadIdx.x;
    const int trow = tid >> 4;
    const int tcol = tid & 15;

    float acc[TM][TN] = {};
    sgemm_core(g_h, Hn, W2, N2, Hn, m0, n0, tid, As, Bs, acc);

    // Fused conv + silu epilogue. 128 | 4096 so no block spans a batch edge.
    const int batch = m0 / Tn;
    const int tt0   = (m0 % Tn) + trow * TM;
    const float* xb = X + (size_t)batch * Tn * Dn;

    #pragma unroll
    for (int dd = 0; dd < 2; dd++) {
        const int d = (n0 + tcol * TN) / Wn + dd;

        float xv[TM + Wn - 1];
        #pragma unroll
        for (int j = 0; j < TM + Wn - 1; j++) {
            int t = tt0 - (Wn - 1) + j;
            xv[j] = (t >= 0) ? xb[(size_t)t * Dn + d] : 0.0f;
        }

        float bias[Wn];
        #pragma unroll
        for (int w = 0; w < Wn; w++) bias[w] = B2[Wn * d + w];

        #pragma unroll
        for (int i = 0; i < TM; i++) {
            float o = 0.0f;
            #pragma unroll
            for (int w = 0; w < Wn; w++)
                o += (acc[i][dd * Wn + w] + bias[w]) * xv[i + w];
            OUT[(size_t)(m0 + trow * TM + i) * Dn + d] = silu_f(o);
        }
    }
}

// ---------------------------------------------------------------------------
extern "C" void kernel_launch(void* const* d_in, const int* in_sizes, int n_in,
                              void* d_out, int out_size) {
    const float* x  = (const float*)d_in[0];   // [4,4096,2048]
    const float* w1 = (const float*)d_in[1];   // [2048,256]
    const float* w2 = (const float*)d_in[2];   // [256,8192]
    const float* b2 = (const float*)d_in[3];   // [8192]
    float* out = (float*)d_out;

    dim3 grid1(Hn / BN, Mn / BM);   // (2, 128)
    gemm1_silu_kernel<<<grid1, NTHREADS>>>(x, w1);

    dim3 grid2(N2 / BN, Mn / BM);   // (64, 128)
    gemm2_conv_kernel<<<grid2, NTHREADS>>>(x, w2, b2, out);
}